// round 15
// baseline (speedup 1.0000x reference)
#include <cuda_runtime.h>
#include <cuda_bf16.h>
#include <cstdint>

#define NN 50000
#define EE 400000
#define DD 300
#define DP 320      // padded feature dim (multiple of 32 for BK; 2 x 160 N-tiles)
#define LL 5
#define CC 128
#define NGG 256
#define BN_EPS 1e-5f
#define NSLOT (2 * LL)
#define PR 64       // rows per block in fuse kernels

// ---------------- device scratch (no allocs allowed) ----------------
__device__ float g_h[NN * DP];        // current node features
__device__ float g_agg[NN * DP];      // h + aggregated neighbors (GEMM1 A)
__device__ float g_z[NN * DP];        // GEMM1 output (pre-BN1)
__device__ float g_zb[NN * DP];       // GEMM2 output (pre-BN2)
__device__ float g_W[2 * LL * DP * DP];
__device__ float g_bias[2 * LL * DP];
__device__ float g_pooled[(LL + 1) * NGG * DP];
__device__ float g_cnt[NGG];
__device__ float g_sum[NSLOT * DP];
__device__ float g_sq[NSLOT * DP];
__device__ float g_scale[NSLOT * DP];
__device__ float g_shift[NSLOT * DP];
__device__ int   g_edge[2 * EE];
__device__ int   g_batch[NN];
__device__ int   g_flag[2];
__device__ int   g_rowptr[NN + 1];
__device__ int   g_cursor[NN];
__device__ int   g_csrc[EE];

// ---------------- setup kernels ----------------
__global__ void k_zero_flags() {
    if (threadIdx.x < 2) g_flag[threadIdx.x] = 0;
}

__global__ void k_detect(const int* __restrict__ raw, int nwords, int slot) {
    int stride = gridDim.x * blockDim.x;
    for (int i = blockIdx.x * blockDim.x + threadIdx.x; 2 * i + 1 < nwords; i += stride) {
        if (raw[2 * i + 1] != 0) g_flag[slot] = 1;  // benign race
    }
}

__global__ void k_convert_edge(const void* __restrict__ raw) {
    int i = blockIdx.x * blockDim.x + threadIdx.x;
    if (i >= 2 * EE) return;
    if (g_flag[0]) g_edge[i] = ((const int*)raw)[i];
    else           g_edge[i] = (int)((const long long*)raw)[i];
}

__global__ void k_convert_batch(const void* __restrict__ raw) {
    int i = blockIdx.x * blockDim.x + threadIdx.x;
    if (i >= NN) return;
    if (g_flag[1]) g_batch[i] = ((const int*)raw)[i];
    else           g_batch[i] = (int)((const long long*)raw)[i];
}

__global__ void k_padW(const float* __restrict__ W1, const float* __restrict__ W2) {
    int total = 2 * LL * DP * DP;
    int stride = gridDim.x * blockDim.x;
    for (int idx = blockIdx.x * blockDim.x + threadIdx.x; idx < total; idx += stride) {
        int c = idx % DP;
        int r = (idx / DP) % DP;
        int l = (idx / (DP * DP)) % LL;
        int w = idx / (DP * DP * LL);
        float v = 0.f;
        if (r < DD && c < DD) {
            const float* W = w ? W2 : W1;
            v = W[(l * DD + r) * DD + c];
        }
        g_W[idx] = v;
    }
}

__global__ void k_padB(const float* __restrict__ b1, const float* __restrict__ b2) {
    int total = 2 * LL * DP;
    int idx = blockIdx.x * blockDim.x + threadIdx.x;
    if (idx >= total) return;
    int c = idx % DP;
    int l = (idx / DP) % LL;
    int w = idx / (DP * LL);
    float v = 0.f;
    if (c < DD) v = (w ? b2 : b1)[l * DD + c];
    g_bias[idx] = v;
}

__global__ void k_zero_pool() {
    int total = (LL + 1) * NGG * DP;
    int stride = gridDim.x * blockDim.x;
    for (int idx = blockIdx.x * blockDim.x + threadIdx.x; idx < total; idx += stride) {
        g_pooled[idx] = 0.f;
        if (idx < NGG) g_cnt[idx] = 0.f;
    }
}

__global__ void k_zero_stats() {
    int idx = blockIdx.x * blockDim.x + threadIdx.x;
    if (idx < NSLOT * DP) { g_sum[idx] = 0.f; g_sq[idx] = 0.f; }
}

// ---------------- CSR build (once per launch) ----------------
__global__ void k_zero_deg() {
    int i = blockIdx.x * blockDim.x + threadIdx.x;
    if (i <= NN) g_rowptr[i] = 0;
}

__global__ void k_hist() {
    int i = blockIdx.x * blockDim.x + threadIdx.x;
    if (i < EE) atomicAdd(&g_rowptr[g_edge[EE + i] + 1], 1);
}

// single block, 1024 threads: inclusive prefix over g_rowptr[1..NN]
__global__ void k_scan() {
    __shared__ int ssum[1024];
    const int CH = (NN + 1023) / 1024;  // 49
    int t = threadIdx.x;
    int beg = t * CH, end = min(beg + CH, NN);
    int s = 0;
    for (int i = beg; i < end; i++) s += g_rowptr[i + 1];
    ssum[t] = s;
    __syncthreads();
    for (int off = 1; off < 1024; off <<= 1) {
        int v = (t >= off) ? ssum[t - off] : 0;
        __syncthreads();
        ssum[t] += v;
        __syncthreads();
    }
    int run = (t > 0) ? ssum[t - 1] : 0;
    for (int i = beg; i < end; i++) {
        run += g_rowptr[i + 1];
        g_rowptr[i + 1] = run;
    }
    if (t == 0) g_rowptr[0] = 0;
}

__global__ void k_copycur() {
    int i = blockIdx.x * blockDim.x + threadIdx.x;
    if (i < NN) g_cursor[i] = g_rowptr[i];
}

__global__ void k_place() {
    int i = blockIdx.x * blockDim.x + threadIdx.x;
    if (i >= EE) return;
    int dst = g_edge[EE + i];
    int pos = atomicAdd(&g_cursor[dst], 1);
    g_csrc[pos] = g_edge[i];
}

// ---------------- aggregation: warp per node, no atomics, 2-way unroll ----------------
// agg[n] = h[n] + sum_{e in csr row n} h[csrc[e]]
__global__ void k_aggregate() {
    int n = (blockIdx.x * blockDim.x + threadIdx.x) >> 5;
    int lane = threadIdx.x & 31;
    if (n >= NN) return;
    int beg = g_rowptr[n], end = g_rowptr[n + 1];
    const float4* hb = (const float4*)g_h;
    const bool l3 = lane < DP / 4 - 64;
    const float4* self = hb + (size_t)n * (DP / 4);
    float4 a0 = self[lane];
    float4 a1 = self[lane + 32];
    float4 a2 = l3 ? self[lane + 64] : make_float4(0.f, 0.f, 0.f, 0.f);
    int e = beg;
    for (; e + 1 < end; e += 2) {
        int s0 = g_csrc[e], s1 = g_csrc[e + 1];
        const float4* r0 = hb + (size_t)s0 * (DP / 4);
        const float4* r1 = hb + (size_t)s1 * (DP / 4);
        float4 u0 = r0[lane],      w0 = r1[lane];
        float4 u1 = r0[lane + 32], w1 = r1[lane + 32];
        float4 u2, w2;
        if (l3) { u2 = r0[lane + 64]; w2 = r1[lane + 64]; }
        a0.x += u0.x + w0.x; a0.y += u0.y + w0.y; a0.z += u0.z + w0.z; a0.w += u0.w + w0.w;
        a1.x += u1.x + w1.x; a1.y += u1.y + w1.y; a1.z += u1.z + w1.z; a1.w += u1.w + w1.w;
        if (l3) {
            a2.x += u2.x + w2.x; a2.y += u2.y + w2.y;
            a2.z += u2.z + w2.z; a2.w += u2.w + w2.w;
        }
    }
    if (e < end) {
        int s = g_csrc[e];
        const float4* sr = hb + (size_t)s * (DP / 4);
        float4 v0 = sr[lane];
        float4 v1 = sr[lane + 32];
        a0.x += v0.x; a0.y += v0.y; a0.z += v0.z; a0.w += v0.w;
        a1.x += v1.x; a1.y += v1.y; a1.z += v1.z; a1.w += v1.w;
        if (l3) {
            float4 v2 = sr[lane + 64];
            a2.x += v2.x; a2.y += v2.y; a2.z += v2.z; a2.w += v2.w;
        }
    }
    float4* d = (float4*)(g_agg + (size_t)n * DP);
    d[lane] = a0;
    d[lane + 32] = a1;
    if (l3) d[lane + 64] = a2;
}

// ---------------- fused init: x -> h (padded), pool depth0 + counts ----------------
__global__ void k_initfuse(const float* __restrict__ x) {
    int c = threadIdx.x;  // 0..319
    int r0 = blockIdx.x * PR;
    int rend = min(r0 + PR, NN);
    if (r0 >= NN) return;
    int curg = g_batch[r0];
    float acc = 0.f;
    int cnt = 0;
    for (int r = r0; r < rend; r++) {
        int gg = g_batch[r];
        if (gg != curg) {
            atomicAdd(&g_pooled[(size_t)curg * DP + c], acc);
            if (c == 0) atomicAdd(&g_cnt[curg], (float)cnt);
            curg = gg; acc = 0.f; cnt = 0;
        }
        float v = (c < DD) ? x[(size_t)r * DD + c] : 0.f;
        g_h[(size_t)r * DP + c] = v;
        acc += v;
        cnt++;
    }
    atomicAdd(&g_pooled[(size_t)curg * DP + c], acc);
    if (c == 0) atomicAdd(&g_cnt[curg], (float)cnt);
}

// stats -> per-column scale/shift (one block of DP threads)
__global__ void k_bnprep(int slot, const float* __restrict__ gamma,
                         const float* __restrict__ beta) {
    int c = threadIdx.x;
    if (c >= DP) return;
    float sc = 0.f, sh = 0.f;
    if (c < DD) {
        const float invn = 1.0f / (float)NN;
        float mean = g_sum[slot * DP + c] * invn;
        float var = g_sq[slot * DP + c] * invn - mean * mean;
        float istd = rsqrtf(var + BN_EPS);
        sc = istd * gamma[c];
        sh = beta[c] - mean * sc;
    }
    g_scale[slot * DP + c] = sc;
    g_shift[slot * DP + c] = sh;
}

// ---------------- fused BN2: h = relu(bn(zb)); pool into depth ----------------
__global__ void k_bnfuse(int slot, int depth) {
    int c = threadIdx.x;  // 0..319
    int r0 = blockIdx.x * PR;
    int rend = min(r0 + PR, NN);
    if (r0 >= NN) return;
    float scl = g_scale[slot * DP + c];
    float shf = g_shift[slot * DP + c];
    float* pbase = g_pooled + (size_t)depth * NGG * DP;
    int curg = g_batch[r0];
    float acc = 0.f;
    for (int r = r0; r < rend; r++) {
        int gg = g_batch[r];
        if (gg != curg) {
            atomicAdd(&pbase[(size_t)curg * DP + c], acc);
            curg = gg; acc = 0.f;
        }
        float v = g_zb[(size_t)r * DP + c];
        v = fmaxf(fmaf(v, scl, shf), 0.f);
        g_h[(size_t)r * DP + c] = v;
        acc += v;
    }
    atomicAdd(&pbase[(size_t)curg * DP + c], acc);
}

// ---------------- TF32 tensor-core GEMM, 128x160 tiles, stats in epilogue ----------
// asel: 0 -> A = g_agg, 1 -> A = g_z.  osel: 0 -> Out = g_z, 1 -> Out = g_zb.
// FUSE=1: A transformed v = relu(v*scale+shift) on load (BN applied on the fly).
// N covered by 2 x 160 tiles (zero waste). Warp tile 64x40 = 4x5 m16n8k8 frags.
#define BKC 32
#define BNT 160
#define ASTRIDE 36
#define BSTRIDE 168
#define ATILE (128 * ASTRIDE)       // 4608 floats
#define BTILE (BKC * BSTRIDE)       // 5376 floats
#define BUFSZ (ATILE + BTILE)       // 9984 floats
#define GEMM_SMEM (2 * BUFSZ * 4)   // 79872 bytes
#define BV4 (BNT / 4)               // 40 float4 per B row

__device__ __forceinline__ void cpa16(uint32_t dst, const void* src, bool pred) {
    int sz = pred ? 16 : 0;
    asm volatile("cp.async.cg.shared.global [%0], [%1], 16, %2;\n"
                 :: "r"(dst), "l"(src), "r"(sz));
}

template <int FUSE>
__global__ void __launch_bounds__(256) k_gemm(int asel, int osel,
                                              int which, int layer,
                                              int slot_in, int slot_out) {
    extern __shared__ float sm[];
    const float* __restrict__ Asrc = asel ? g_z : g_agg;   // device-side symbol resolve
    float* __restrict__ Out = osel ? g_zb : g_z;
    const float* __restrict__ Bw = g_W + ((size_t)which * LL + layer) * DP * DP;
    const float* __restrict__ bias = g_bias + ((size_t)which * LL + layer) * DP;
    const float* __restrict__ scl = g_scale + (size_t)slot_in * DP;
    const float* __restrict__ shf = g_shift + (size_t)slot_in * DP;
    const int bm = blockIdx.y * 128;
    const int bn = blockIdx.x * BNT;
    const int tid = threadIdx.x;
    const int lane = tid & 31, wid = tid >> 5;
    const int wm = (wid & 1) << 6;       // 0 / 64
    const int wn = (wid >> 1) * 40;      // 0/40/80/120
    const int gid = lane >> 2, tk = lane & 3;

    float c[4][5][4];
#pragma unroll
    for (int i = 0; i < 4; i++)
#pragma unroll
        for (int j = 0; j < 5; j++)
#pragma unroll
            for (int f = 0; f < 4; f++) c[i][j][f] = 0.f;

    const int ar = tid >> 3;         // 0..31
    const int av = (tid & 7) << 2;   // 0..28

    uint32_t smb = (uint32_t)__cvta_generic_to_shared(sm);

    // ---------- prologue ----------
    if (FUSE) {
        float4 areg[4];
#pragma unroll
        for (int p = 0; p < 4; p++) {
            int gr = bm + ar + p * 32;
            areg[p] = (gr < NN) ? *(const float4*)(Asrc + (size_t)gr * DP + av)
                                : make_float4(0.f, 0.f, 0.f, 0.f);
        }
#pragma unroll
        for (int i = tid; i < BKC * BV4; i += 256) {
            int r = i / BV4, c4 = i % BV4;
            cpa16(smb + (uint32_t)((ATILE + r * BSTRIDE + c4 * 4) * 4),
                  Bw + (size_t)r * DP + bn + c4 * 4, true);
        }
        asm volatile("cp.async.commit_group;\n");
        float sc0 = scl[av], sc1 = scl[av + 1], sc2 = scl[av + 2], sc3 = scl[av + 3];
        float sh0 = shf[av], sh1 = shf[av + 1], sh2 = shf[av + 2], sh3 = shf[av + 3];
#pragma unroll
        for (int p = 0; p < 4; p++) {
            float4 v = areg[p];
            v.x = fmaxf(fmaf(v.x, sc0, sh0), 0.f);
            v.y = fmaxf(fmaf(v.y, sc1, sh1), 0.f);
            v.z = fmaxf(fmaf(v.z, sc2, sh2), 0.f);
            v.w = fmaxf(fmaf(v.w, sc3, sh3), 0.f);
            float* d = sm + (ar + p * 32) * ASTRIDE + av;
            d[0] = v.x; d[1] = v.y; d[2] = v.z; d[3] = v.w;
        }
    } else {
#pragma unroll
        for (int p = 0; p < 4; p++) {
            int gr = bm + ar + p * 32;
            const float* asrc = Asrc + (size_t)(gr < NN ? gr : 0) * DP + av;
            cpa16(smb + (uint32_t)(((ar + p * 32) * ASTRIDE + av) * 4), asrc, gr < NN);
        }
#pragma unroll
        for (int i = tid; i < BKC * BV4; i += 256) {
            int r = i / BV4, c4 = i % BV4;
            cpa16(smb + (uint32_t)((ATILE + r * BSTRIDE + c4 * 4) * 4),
                  Bw + (size_t)r * DP + bn + c4 * 4, true);
        }
        asm volatile("cp.async.commit_group;\n");
    }

    int buf = 0;
#pragma unroll 1
    for (int k0 = 0; k0 < DP; k0 += BKC) {
        const bool has = (k0 + BKC < DP);
        float4 areg[4];
        float sc0, sc1, sc2, sc3, sh0, sh1, sh2, sh3;
        if (has) {
            int nb = buf ^ 1;
            int k1 = k0 + BKC;
            if (FUSE) {
#pragma unroll
                for (int p = 0; p < 4; p++) {
                    int gr = bm + ar + p * 32;
                    areg[p] = (gr < NN)
                        ? *(const float4*)(Asrc + (size_t)gr * DP + k1 + av)
                        : make_float4(0.f, 0.f, 0.f, 0.f);
                }
                sc0 = scl[k1 + av]; sc1 = scl[k1 + av + 1];
                sc2 = scl[k1 + av + 2]; sc3 = scl[k1 + av + 3];
                sh0 = shf[k1 + av]; sh1 = shf[k1 + av + 1];
                sh2 = shf[k1 + av + 2]; sh3 = shf[k1 + av + 3];
            } else {
#pragma unroll
                for (int p = 0; p < 4; p++) {
                    int gr = bm + ar + p * 32;
                    const float* asrc = Asrc + (size_t)(gr < NN ? gr : 0) * DP + k1 + av;
                    cpa16(smb + (uint32_t)((nb * BUFSZ + (ar + p * 32) * ASTRIDE + av) * 4),
                          asrc, gr < NN);
                }
            }
#pragma unroll
            for (int i = tid; i < BKC * BV4; i += 256) {
                int r = i / BV4, c4 = i % BV4;
                cpa16(smb + (uint32_t)((nb * BUFSZ + ATILE + r * BSTRIDE + c4 * 4) * 4),
                      Bw + (size_t)(k1 + r) * DP + bn + c4 * 4, true);
            }
            asm volatile("cp.async.commit_group;\n");
            asm volatile("cp.async.wait_group 1;\n");
        } else {
            asm volatile("cp.async.wait_group 0;\n");
        }
        __syncthreads();
        const float* As = sm + buf * BUFSZ;
        const float* Bs = As + ATILE;
#pragma unroll
        for (int ks = 0; ks < BKC; ks += 8) {
            uint32_t a[4][4], b[5][2];
#pragma unroll
            for (int mt = 0; mt < 4; mt++) {
                const float* ap = As + (wm + mt * 16 + gid) * ASTRIDE + ks + tk;
                a[mt][0] = __float_as_uint(ap[0]);
                a[mt][1] = __float_as_uint(ap[8 * ASTRIDE]);
                a[mt][2] = __float_as_uint(ap[4]);
                a[mt][3] = __float_as_uint(ap[8 * ASTRIDE + 4]);
            }
#pragma unroll
            for (int nt = 0; nt < 5; nt++) {
                const float* bp = Bs + (ks + tk) * BSTRIDE + wn + nt * 8 + gid;
                b[nt][0] = __float_as_uint(bp[0]);
                b[nt][1] = __float_as_uint(bp[4 * BSTRIDE]);
            }
#pragma unroll
            for (int mt = 0; mt < 4; mt++)
#pragma unroll
                for (int nt = 0; nt < 5; nt++)
                    asm volatile(
                        "mma.sync.aligned.m16n8k8.row.col.f32.tf32.tf32.f32 "
                        "{%0,%1,%2,%3}, {%4,%5,%6,%7}, {%8,%9}, {%0,%1,%2,%3};\n"
                        : "+f"(c[mt][nt][0]), "+f"(c[mt][nt][1]),
                          "+f"(c[mt][nt][2]), "+f"(c[mt][nt][3])
                        : "r"(a[mt][0]), "r"(a[mt][1]), "r"(a[mt][2]), "r"(a[mt][3]),
                          "r"(b[nt][0]), "r"(b[nt][1]));
        }
        __syncthreads();
        if (FUSE && has) {
            int nb = buf ^ 1;
#pragma unroll
            for (int p = 0; p < 4; p++) {
                float4 v = areg[p];
                v.x = fmaxf(fmaf(v.x, sc0, sh0), 0.f);
                v.y = fmaxf(fmaf(v.y, sc1, sh1), 0.f);
                v.z = fmaxf(fmaf(v.z, sc2, sh2), 0.f);
                v.w = fmaxf(fmaf(v.w, sc3, sh3), 0.f);
                float* d = sm + nb * BUFSZ + (ar + p * 32) * ASTRIDE + av;
                d[0] = v.x; d[1] = v.y; d[2] = v.z; d[3] = v.w;
            }
        }
        buf ^= 1;
    }

    // ---------- epilogue: store + bias, fused column stats ----------
    float* Sg = g_sum + (size_t)slot_out * DP;
    float* Qg = g_sq + (size_t)slot_out * DP;
#pragma unroll
    for (int nt = 0; nt < 5; nt++) {
        int c0 = bn + wn + nt * 8 + 2 * tk;   // always < DP
        float b0 = bias[c0], b1 = bias[c0 + 1];
        float s0 = 0.f, q0 = 0.f, s1 = 0.f, q1 = 0.f;
#pragma unroll
        for (int mt = 0; mt < 4; mt++) {
            int r0 = bm + wm + mt * 16 + gid;
            float v00 = c[mt][nt][0] + b0, v01 = c[mt][nt][1] + b1;
            float v10 = c[mt][nt][2] + b0, v11 = c[mt][nt][3] + b1;
            if (r0 < NN) {
                *(float2*)(Out + (size_t)r0 * DP + c0) = make_float2(v00, v01);
                s0 += v00; q0 += v00 * v00;
                s1 += v01; q1 += v01 * v01;
            }
            if (r0 + 8 < NN) {
                *(float2*)(Out + (size_t)(r0 + 8) * DP + c0) = make_float2(v10, v11);
                s0 += v10; q0 += v10 * v10;
                s1 += v11; q1 += v11 * v11;
            }
        }
#pragma unroll
        for (int off = 16; off >= 4; off >>= 1) {
            s0 += __shfl_xor_sync(0xffffffffu, s0, off);
            q0 += __shfl_xor_sync(0xffffffffu, q0, off);
            s1 += __shfl_xor_sync(0xffffffffu, s1, off);
            q1 += __shfl_xor_sync(0xffffffffu, q1, off);
        }
        if (gid == 0) {
            atomicAdd(&Sg[c0], s0);
            atomicAdd(&Qg[c0], q0);
            atomicAdd(&Sg[c0 + 1], s1);
            atomicAdd(&Qg[c0 + 1], q1);
        }
    }
}

// ---------------- readout ----------------
__global__ void k_readout(const float* __restrict__ fcW, const float* __restrict__ fcb,
                          float* __restrict__ out) {
    int g = blockIdx.x;
    int c = threadIdx.x;  // 128
    float inv = 1.0f / fmaxf(g_cnt[g], 1.0f);
    float acc = 0.f;
#pragma unroll
    for (int i = 0; i <= LL; ++i) {
        const float* p = g_pooled + ((size_t)i * NGG + g) * DP;
        const float* W = fcW + (size_t)i * DD * CC;
        float a = 0.f;
        for (int k = 0; k < DD; ++k)
            a += p[k] * W[k * CC + c];
        acc += inv * a + fcb[i * CC + c];
    }
    out[g * CC + c] = acc;
}

// ---------------- launch ----------------
extern "C" void kernel_launch(void* const* d_in, const int* in_sizes, int n_in,
                              void* d_out, int out_size) {
    const float* x       = (const float*)d_in[0];
    const void*  edg_raw = d_in[1];
    const void*  bat_raw = d_in[2];
    const float* mlp_W1  = (const float*)d_in[3];
    const float* mlp_b1  = (const float*)d_in[4];
    const float* mlp_g1  = (const float*)d_in[5];
    const float* mlp_be1 = (const float*)d_in[6];
    const float* mlp_W2  = (const float*)d_in[7];
    const float* mlp_b2  = (const float*)d_in[8];
    const float* bn_g    = (const float*)d_in[9];
    const float* bn_b    = (const float*)d_in[10];
    const float* fc_W    = (const float*)d_in[11];
    const float* fc_b    = (const float*)d_in[12];
    float* out = (float*)d_out;

    static bool done = false;
    if (!done) {
        cudaFuncSetAttribute(k_gemm<0>, cudaFuncAttributeMaxDynamicSharedMemorySize, GEMM_SMEM);
        cudaFuncSetAttribute(k_gemm<1>, cudaFuncAttributeMaxDynamicSharedMemorySize, GEMM_SMEM);
        done = true;
    }

    // dtype normalization (int64 vs int32)
    k_zero_flags<<<1, 32>>>();
    k_detect<<<256, 256>>>((const int*)edg_raw, 2 * EE, 0);
    k_detect<<<64, 256>>>((const int*)bat_raw, NN, 1);
    k_convert_edge<<<(2 * EE + 255) / 256, 256>>>(edg_raw);
    k_convert_batch<<<(NN + 255) / 256, 256>>>(bat_raw);

    // CSR build (once)
    k_zero_deg<<<(NN + 256) / 256, 256>>>();
    k_hist<<<(EE + 255) / 256, 256>>>();
    k_scan<<<1, 1024>>>();
    k_copycur<<<(NN + 255) / 256, 256>>>();
    k_place<<<(EE + 255) / 256, 256>>>();

    // param staging + init
    k_padW<<<1024, 256>>>(mlp_W1, mlp_W2);
    k_padB<<<(2 * LL * DP + 255) / 256, 256>>>(mlp_b1, mlp_b2);
    k_zero_pool<<<1024, 256>>>();
    k_zero_stats<<<(NSLOT * DP + 255) / 256, 256>>>();
    k_initfuse<<<(NN + PR - 1) / PR, DP>>>(x);

    dim3 ggrid(DP / BNT, (NN + 127) / 128);
    for (int i = 0; i < LL; ++i) {
        k_aggregate<<<(NN * 32 + 255) / 256, 256>>>();
        // GEMM1: z = agg @ W1 + b1, stats slot 2i
        k_gemm<0><<<ggrid, 256, GEMM_SMEM>>>(0, 0, 0, i, 0, 2 * i);
        k_bnprep<<<1, DP>>>(2 * i, mlp_g1 + i * DD, mlp_be1 + i * DD);
        // GEMM2: zb = relu(bn1(z)) @ W2 + b2, BN fused on A-load, stats slot 2i+1
        k_gemm<1><<<ggrid, 256, GEMM_SMEM>>>(1, 1, 1, i, 2 * i, 2 * i + 1);
        k_bnprep<<<1, DP>>>(2 * i + 1, bn_g + i * DD, bn_b + i * DD);
        // h = relu(bn2(zb)); pool depth i+1
        k_bnfuse<<<(NN + PR - 1) / PR, DP>>>(2 * i + 1, i + 1);
    }
    k_readout<<<NGG, CC>>>(fc_W, fc_b, out);
}